// round 14
// baseline (speedup 1.0000x reference)
#include <cuda_runtime.h>
#include <math.h>

#define B 4
#define L 2048
#define H 8
#define D 64
#define S 40
#define U 40
#define HD (H*D)
#define CHUNK 128
#define NCHUNK (L/CHUNK)     /* 16 scan chunks */
#define SCALE 0.125f         /* 1/sqrt(64) */

// scratch (allocation-free rule: __device__ globals)
__device__ float g_M[B*H*L];
__device__ int   g_top[B*H*U];
__device__ float g_agg[B*H*NCHUNK*D];    // scan chunk aggregates
__device__ int   g_flag[B*H*NCHUNK];     // lookback flags

// ---------------------------------------------------------------------------
// Kernel 0: clear lookback flags (runs in scan stream, before scan).
// ---------------------------------------------------------------------------
__global__ void clear_flags_kernel() {
    g_flag[threadIdx.x] = 0;             // 512 threads = B*H*NCHUNK
}

// ---------------------------------------------------------------------------
// Kernel 1: M[b,h,q] = max_s dot(Q[b,h,q], K[b,h,idx[q,s]]) - sum_s/L
// One warp per (b,h,q). 4 groups of 8 lanes; each group owns one key per
// batch and reads its 256B row as 2x(8 lanes x 16B) = ONE 128B line per LDG.
// ---------------------------------------------------------------------------
__global__ void compute_M_kernel(const float* __restrict__ Q,
                                 const float* __restrict__ K,
                                 const int*   __restrict__ idx) {
    int gw   = (blockIdx.x * blockDim.x + threadIdx.x) >> 5;
    int lane = threadIdx.x & 31;
    if (gw >= B*H*L) return;
    int q = gw % L;
    int h = (gw / L) % H;
    int b = gw / (L*H);
    int g   = lane >> 3;     // group 0..3: which key in the batch
    int sub = lane & 7;      // 16B slice within the 128B half-row

    const float4* qrow = (const float4*)(Q + ((size_t)b*L + q)*HD + (size_t)h*D);
    float4 q0 = qrow[sub];        // dims [4*sub   .. 4*sub+3]
    float4 q1 = qrow[8 + sub];    // dims [32+4*sub .. ]

    int k0v = __ldg(idx + q*S + lane);
    int k1v = (lane < 8) ? __ldg(idx + q*S + 32 + lane) : 0;

    const size_t bhK = ((size_t)b*L)*HD + (size_t)h*D;

    float mx = -INFINITY, sm = 0.f;
    #pragma unroll
    for (int t = 0; t < 10; t++) {
        int srcl = t*4 + g;
        int kk = (srcl < 32) ? __shfl_sync(0xffffffffu, k0v, srcl)
                             : __shfl_sync(0xffffffffu, k1v, srcl - 32);
        const float4* krow = (const float4*)(K + bhK + (size_t)kk*HD);
        float4 k0 = krow[sub];
        float4 k1 = krow[8 + sub];
        float p = q0.x*k0.x + q0.y*k0.y + q0.z*k0.z + q0.w*k0.w
                + q1.x*k1.x + q1.y*k1.y + q1.z*k1.z + q1.w*k1.w;
        // reduce within the 8-lane group -> full 64-dim dot on every lane
        p += __shfl_xor_sync(0xffffffffu, p, 1);
        p += __shfl_xor_sync(0xffffffffu, p, 2);
        p += __shfl_xor_sync(0xffffffffu, p, 4);
        mx = fmaxf(mx, p);
        sm += p;
    }
    // reduce across the 4 groups
    mx = fmaxf(mx, __shfl_xor_sync(0xffffffffu, mx, 8));
    sm += __shfl_xor_sync(0xffffffffu, sm, 8);
    mx = fmaxf(mx, __shfl_xor_sync(0xffffffffu, mx, 16));
    sm += __shfl_xor_sync(0xffffffffu, sm, 16);

    if (lane == 0) g_M[gw] = mx - sm * (1.0f/(float)L);
}

// ---------------------------------------------------------------------------
// Kernel 2: top-40 per (b,h), descending, ties -> smaller index (lax.top_k).
// One warp per (b,h); register-resident order-preserving uint32 values,
// packed (val, ~idx) u64 butterfly max; loser lane rescans its 64 slots.
// ---------------------------------------------------------------------------
__device__ __forceinline__ unsigned order_f32(float v) {
    unsigned u = __float_as_uint(v);
    return (u & 0x80000000u) ? ~u : (u | 0x80000000u);
}

__global__ void topk_kernel() {
    int bh   = blockIdx.x;
    int lane = threadIdx.x;           // block = 32
    const float* M = g_M + bh*L;

    unsigned ov[64];
    #pragma unroll
    for (int j = 0; j < 64; j++) ov[j] = order_f32(M[j*32 + lane]);

    unsigned long long removed = 0ull;
    unsigned bv = 0; int bslot = 0;
    #pragma unroll
    for (int j = 0; j < 64; j++) if (ov[j] > bv) { bv = ov[j]; bslot = j; }

    for (int u = 0; u < U; u++) {
        unsigned long long key =
            ((unsigned long long)bv << 32) | (unsigned)(~(unsigned)(bslot*32 + lane));
        #pragma unroll
        for (int o = 16; o > 0; o >>= 1) {
            unsigned long long ok = __shfl_xor_sync(0xffffffffu, key, o);
            if (ok > key) key = ok;
        }
        int widx = (int)(~(unsigned)key);
        if (lane == 0) g_top[bh*U + u] = widx;
        if ((widx & 31) == lane) {
            removed |= 1ull << (widx >> 5);
            bv = 0; bslot = 0;
            #pragma unroll
            for (int j = 0; j < 64; j++) {
                unsigned v = ((removed >> j) & 1ull) ? 0u : ov[j];
                if (v > bv) { bv = v; bslot = j; }
            }
        }
    }
}

// ---------------------------------------------------------------------------
// Kernel 3: fused cumsum(V) over L via decoupled lookback. One kernel, one V
// read, one out write. Block = (bh, c); all 512 blocks resident in one wave.
// (Exact form that passed at R7/R8/R13.)
// ---------------------------------------------------------------------------
__global__ void scan_kernel(const float* __restrict__ V, float* __restrict__ out) {
    int blk = blockIdx.x;
    int c   = blk & (NCHUNK-1);
    int bh  = blk >> 4;
    int h   = bh & (H-1), b = bh >> 3;
    int t   = threadIdx.x;            // 256
    __shared__ float tile[CHUNK*D];   // 32KB
    __shared__ float part[4][64];
    __shared__ float offs[4][64];

    size_t base = (((size_t)b*L + (size_t)c*CHUNK))*HD + (size_t)h*D;
    for (int e = t; e < CHUNK*D/4; e += 256) {
        int q = e >> 4, d4 = e & 15;
        ((float4*)tile)[q*16 + d4] = *(const float4*)(V + base + (size_t)q*HD + d4*4);
    }
    __syncthreads();

    // intra-part serial scan: 4 parts x 64 d-lanes, 32 rows each
    int p = t >> 6, d = t & 63;
    {
        float acc = 0.f;
        #pragma unroll
        for (int i = 0; i < 32; i++) {
            acc += tile[(p*32 + i)*64 + d];
            tile[(p*32 + i)*64 + d] = acc;
        }
        part[p][d] = acc;
    }
    __syncthreads();

    // publish chunk aggregate (release)
    if (t < 64) g_agg[blk*D + t] = part[0][t] + part[1][t] + part[2][t] + part[3][t];
    __syncthreads();
    if (t == 0) { __threadfence(); atomicExch(&g_flag[blk], 1); }

    // lookback: wait for all predecessors, then sum their aggregates
    if (t < c) while (atomicAdd(&g_flag[bh*NCHUNK + t], 0) == 0) {}
    __syncthreads();
    __threadfence();
    if (t < 64) {
        float o = 0.f;
        for (int cc = 0; cc < c; cc++) o += g_agg[(bh*NCHUNK + cc)*D + t];
        offs[0][t] = o;          o += part[0][t];
        offs[1][t] = o;          o += part[1][t];
        offs[2][t] = o;          o += part[2][t];
        offs[3][t] = o;
    }
    __syncthreads();

    for (int e = t; e < CHUNK*D/4; e += 256) {
        int q = e >> 4, d4 = e & 15;
        float4 v  = ((float4*)tile)[q*16 + d4];
        const float* ofp = &offs[q >> 5][d4*4];
        v.x += ofp[0]; v.y += ofp[1]; v.z += ofp[2]; v.w += ofp[3];
        *(float4*)(out + base + (size_t)q*HD + d4*4) = v;
    }
}

// ---------------------------------------------------------------------------
// Kernel 4: attention for the 40 selected queries per (b,h); scatter into out.
// Rank-i row attends only keys 0..i (Informer mask quirk: mask is triu(u,L)).
// Grid = (bh, group of 4 rows) = 320 blocks of 128; one warp per output row.
// Loads only the K/V rows its group can reference (0..4g+3).
// ---------------------------------------------------------------------------
__global__ void attn_kernel(const float* __restrict__ Q,
                            const float* __restrict__ K,
                            const float* __restrict__ V,
                            float* __restrict__ out) {
    int g  = blockIdx.x % 10;
    int bh = blockIdx.x / 10;
    int h  = bh & (H-1), b = bh >> 3;
    int t  = threadIdx.x;     // 128 = 4 warps
    __shared__ float Ks[U][D+1], Vs[U][D+1], Qs[4][D+1];
    __shared__ int ti[4];

    if (t < 4) ti[t] = g_top[bh*U + g*4 + t];
    __syncthreads();

    int kmax = g*4 + 4;                           // rows 0..kmax-1 needed
    for (int e = t; e < kmax*D; e += 128) {
        int r = e >> 6, d = e & 63;
        Ks[r][d] = K[((size_t)b*L + r)*HD + (size_t)h*D + d];
        Vs[r][d] = V[((size_t)b*L + r)*HD + (size_t)h*D + d];
    }
    for (int e = t; e < 4*D; e += 128) {
        int r = e >> 6, d = e & 63;
        Qs[r][d] = Q[((size_t)b*L + ti[r])*HD + (size_t)h*D + d];
    }
    __syncthreads();

    int warp = t >> 5, lane = t & 31;
    int i   = g*4 + warp;                         // output row rank 0..39
    int k1  = (lane < kmax) ? lane : 0;           // clamp to loaded rows
    int k2l = lane + 32;
    int k2  = (k2l < kmax) ? k2l : 0;

    bool v0 = (lane <= i);
    bool v1 = (k2l < U) && (k2l <= i);

    float s0 = 0.f, s1 = 0.f;
    #pragma unroll
    for (int d = 0; d < D; d++) {
        float qd = Qs[warp][d];
        s0 += qd * Ks[k1][d];
        s1 += qd * Ks[k2][d];
    }
    s0 *= SCALE; s1 *= SCALE;

    float mx = fmaxf(v0 ? s0 : -INFINITY, v1 ? s1 : -INFINITY);
    #pragma unroll
    for (int o = 16; o > 0; o >>= 1)
        mx = fmaxf(mx, __shfl_xor_sync(0xffffffffu, mx, o));

    float e0 = v0 ? __expf(s0 - mx) : 0.f;
    float e1 = v1 ? __expf(s1 - mx) : 0.f;
    float den = e0 + e1;
    #pragma unroll
    for (int o = 16; o > 0; o >>= 1)
        den += __shfl_xor_sync(0xffffffffu, den, o);
    float inv = __frcp_rn(den);
    float w0 = e0 * inv, w1 = e1 * inv;

    float a0 = 0.f, a1 = 0.f;
    int klim = (i < 31) ? i : 31;
    for (int k = 0; k <= klim; k++) {
        float w = __shfl_sync(0xffffffffu, w0, k);
        a0 += w * Vs[k][lane];
        a1 += w * Vs[k][lane+32];
    }
    for (int k = 32; k <= i; k++) {               // only when i >= 32
        float w = __shfl_sync(0xffffffffu, w1, k - 32);
        a0 += w * Vs[k][lane];
        a1 += w * Vs[k][lane+32];
    }

    float* op = out + ((size_t)b*L + ti[warp])*HD + (size_t)h*D;
    op[lane]      = a0;
    op[lane + 32] = a1;
}

// ---------------------------------------------------------------------------
// Launch: fork scan branch onto a second stream so the cumsum (V-only) runs
// concurrently with compute_M/topk (Q/K/idx-only); attn joins both.
// Streams/events are created lazily on the first (non-captured) call and
// reused; all subsequent work is async and graph-capturable.
// ---------------------------------------------------------------------------
extern "C" void kernel_launch(void* const* d_in, const int* in_sizes, int n_in,
                              void* d_out, int out_size) {
    const float* Q   = (const float*)d_in[0];
    const float* K   = (const float*)d_in[1];
    const float* V   = (const float*)d_in[2];
    const int*   idx = (const int*)d_in[3];
    float* out = (float*)d_out;

    static cudaStream_t s1 = nullptr;
    static cudaEvent_t  e_fork = nullptr, e_scan = nullptr;
    if (s1 == nullptr) {
        cudaStreamCreateWithFlags(&s1, cudaStreamNonBlocking);
        cudaEventCreateWithFlags(&e_fork, cudaEventDisableTiming);
        cudaEventCreateWithFlags(&e_scan, cudaEventDisableTiming);
    }

    // fork: scan branch on s1
    cudaEventRecord(e_fork, 0);
    cudaStreamWaitEvent(s1, e_fork, 0);
    clear_flags_kernel<<<1, B*H*NCHUNK, 0, s1>>>();
    scan_kernel<<<B*H*NCHUNK, 256, 0, s1>>>(V, out);
    cudaEventRecord(e_scan, s1);

    // main branch: M scores -> topk (independent of scan)
    compute_M_kernel<<<B*H*L*32/256, 256>>>(Q, K, idx);
    topk_kernel<<<B*H, 32>>>();

    // join: attn needs topk (same stream) and scan's out-writes (event)
    cudaStreamWaitEvent(0, e_scan, 0);
    attn_kernel<<<B*H*10, 128>>>(Q, K, V, out);
}

// round 15
// speedup vs baseline: 1.0966x; 1.0966x over previous
#include <cuda_runtime.h>
#include <math.h>

#define B 4
#define L 2048
#define H 8
#define D 64
#define S 40
#define U 40
#define HD (H*D)
#define CHUNK 128
#define NCHUNK (L/CHUNK)     /* 16 scan chunks */
#define SCALE 0.125f         /* 1/sqrt(64) */

// scratch (allocation-free rule: __device__ globals)
__device__ float g_M[B*H*L];
__device__ int   g_top[B*H*U];
__device__ float g_agg[B*H*NCHUNK*D];    // scan chunk aggregates
__device__ int   g_flag[B*H*NCHUNK];     // lookback flags

// ---------------------------------------------------------------------------
// Kernel 0: clear lookback flags (runs in scan stream, before scan).
// ---------------------------------------------------------------------------
__global__ void clear_flags_kernel() {
    g_flag[threadIdx.x] = 0;             // 512 threads = B*H*NCHUNK
}

// ---------------------------------------------------------------------------
// Kernel 1: M[b,h,q] = max_s dot(Q[b,h,q], K[b,h,idx[q,s]]) - sum_s/L
// One warp per (b,h,q). 4 groups of 8 lanes; each group owns one key per
// batch and reads its 256B row as 2x(8 lanes x 16B) = ONE 128B line per LDG.
// ---------------------------------------------------------------------------
__global__ void compute_M_kernel(const float* __restrict__ Q,
                                 const float* __restrict__ K,
                                 const int*   __restrict__ idx) {
    int gw   = (blockIdx.x * blockDim.x + threadIdx.x) >> 5;
    int lane = threadIdx.x & 31;
    if (gw >= B*H*L) return;
    int q = gw % L;
    int h = (gw / L) % H;
    int b = gw / (L*H);
    int g   = lane >> 3;     // group 0..3: which key in the batch
    int sub = lane & 7;      // 16B slice within the 128B half-row

    const float4* qrow = (const float4*)(Q + ((size_t)b*L + q)*HD + (size_t)h*D);
    float4 q0 = qrow[sub];        // dims [4*sub   .. 4*sub+3]
    float4 q1 = qrow[8 + sub];    // dims [32+4*sub .. ]

    int k0v = __ldg(idx + q*S + lane);
    int k1v = (lane < 8) ? __ldg(idx + q*S + 32 + lane) : 0;

    const size_t bhK = ((size_t)b*L)*HD + (size_t)h*D;

    float mx = -INFINITY, sm = 0.f;
    #pragma unroll
    for (int t = 0; t < 10; t++) {
        int srcl = t*4 + g;
        int kk = (srcl < 32) ? __shfl_sync(0xffffffffu, k0v, srcl)
                             : __shfl_sync(0xffffffffu, k1v, srcl - 32);
        const float4* krow = (const float4*)(K + bhK + (size_t)kk*HD);
        float4 k0 = krow[sub];
        float4 k1 = krow[8 + sub];
        float p = q0.x*k0.x + q0.y*k0.y + q0.z*k0.z + q0.w*k0.w
                + q1.x*k1.x + q1.y*k1.y + q1.z*k1.z + q1.w*k1.w;
        // reduce within the 8-lane group -> full 64-dim dot on every lane
        p += __shfl_xor_sync(0xffffffffu, p, 1);
        p += __shfl_xor_sync(0xffffffffu, p, 2);
        p += __shfl_xor_sync(0xffffffffu, p, 4);
        mx = fmaxf(mx, p);
        sm += p;
    }
    // reduce across the 4 groups
    mx = fmaxf(mx, __shfl_xor_sync(0xffffffffu, mx, 8));
    sm += __shfl_xor_sync(0xffffffffu, sm, 8);
    mx = fmaxf(mx, __shfl_xor_sync(0xffffffffu, mx, 16));
    sm += __shfl_xor_sync(0xffffffffu, sm, 16);

    if (lane == 0) g_M[gw] = mx - sm * (1.0f/(float)L);
}

// ---------------------------------------------------------------------------
// Kernel 2: top-40 per (b,h) via block-parallel 1-bit MSB radix select.
// 256 threads/bh, 8 register values each (order-preserving uint32 map).
// Finds exact 40th-largest value T, compacts >T and ==T candidates, assigns
// ranks by pairwise count (value desc, index asc == lax.top_k semantics).
// ---------------------------------------------------------------------------
__device__ __forceinline__ unsigned order_f32(float v) {
    unsigned u = __float_as_uint(v);
    return (u & 0x80000000u) ? ~u : (u | 0x80000000u);
}

__global__ void topk_kernel() {
    int bh = blockIdx.x;
    int t  = threadIdx.x;              // 256
    const float* M = g_M + bh*L;

    unsigned v[8];
    #pragma unroll
    for (int j = 0; j < 8; j++) v[j] = order_f32(M[j*256 + t]);

    __shared__ int      s_cnt;
    __shared__ unsigned s_prefix;
    __shared__ int      s_k;
    if (t == 0) { s_prefix = 0u; s_k = U; s_cnt = 0; }
    __syncthreads();

    // 32 one-bit passes: after pass b, s_prefix holds bits 31..b of T
    for (int b = 31; b >= 0; b--) {
        unsigned test = s_prefix | (1u << b);
        int c = 0;
        #pragma unroll
        for (int j = 0; j < 8; j++) c += ((v[j] >> b) == (test >> b));
        #pragma unroll
        for (int o = 16; o > 0; o >>= 1) c += __shfl_xor_sync(0xffffffffu, c, o);
        if ((t & 31) == 0) atomicAdd(&s_cnt, c);
        __syncthreads();
        if (t == 0) {
            if (s_cnt >= s_k) s_prefix = test;
            else              s_k -= s_cnt;
            s_cnt = 0;
        }
        __syncthreads();
    }
    unsigned T = s_prefix;             // exact 40th-largest value

    // compact candidates
    __shared__ int      nGT, nTie;
    __shared__ unsigned selval[48];
    __shared__ int      selidx[48], tieidx[48];
    if (t == 0) { nGT = 0; nTie = 0; }
    __syncthreads();
    #pragma unroll
    for (int j = 0; j < 8; j++) {
        if (v[j] > T) {
            int p = atomicAdd(&nGT, 1);
            if (p < 48) { selval[p] = v[j]; selidx[p] = j*256 + t; }
        } else if (v[j] == T) {
            int p = atomicAdd(&nTie, 1);
            if (p < 48) tieidx[p] = j*256 + t;
        }
    }
    __syncthreads();

    int n1 = nGT;                      // #elements strictly above T  (< 40)
    int ntake = U - n1;                // #ties at T to take (smallest indices)

    // ranks for >T candidates: pairwise (value desc, index asc)
    if (t < n1) {
        unsigned mv = selval[t]; int mi = selidx[t];
        int r = 0;
        for (int j = 0; j < n1; j++) {
            unsigned ov2 = selval[j];
            r += (ov2 > mv) || (ov2 == mv && selidx[j] < mi);
        }
        g_top[bh*U + r] = mi;
    }
    // ties at T: smallest ntake indices get ranks n1..39 in ascending order
    if (t < 32) {
        int nt = (nTie < 48) ? nTie : 48;
        for (int i = t; i < nt; i += 32) {
            int mi = tieidx[i];
            int r = 0;
            for (int j = 0; j < nt; j++) r += (tieidx[j] < mi);
            if (r < ntake) g_top[bh*U + n1 + r] = mi;
        }
    }
}

// ---------------------------------------------------------------------------
// Kernel 3: fused cumsum(V) over L via decoupled lookback. One kernel, one V
// read, one out write. Block = (bh, c); all 512 blocks resident in one wave.
// (Exact form that passed at R7/R8/R13/R14.)
// ---------------------------------------------------------------------------
__global__ void scan_kernel(const float* __restrict__ V, float* __restrict__ out) {
    int blk = blockIdx.x;
    int c   = blk & (NCHUNK-1);
    int bh  = blk >> 4;
    int h   = bh & (H-1), b = bh >> 3;
    int t   = threadIdx.x;            // 256
    __shared__ float tile[CHUNK*D];   // 32KB
    __shared__ float part[4][64];
    __shared__ float offs[4][64];

    size_t base = (((size_t)b*L + (size_t)c*CHUNK))*HD + (size_t)h*D;
    for (int e = t; e < CHUNK*D/4; e += 256) {
        int q = e >> 4, d4 = e & 15;
        ((float4*)tile)[q*16 + d4] = *(const float4*)(V + base + (size_t)q*HD + d4*4);
    }
    __syncthreads();

    // intra-part serial scan: 4 parts x 64 d-lanes, 32 rows each
    int p = t >> 6, d = t & 63;
    {
        float acc = 0.f;
        #pragma unroll
        for (int i = 0; i < 32; i++) {
            acc += tile[(p*32 + i)*64 + d];
            tile[(p*32 + i)*64 + d] = acc;
        }
        part[p][d] = acc;
    }
    __syncthreads();

    // publish chunk aggregate (release)
    if (t < 64) g_agg[blk*D + t] = part[0][t] + part[1][t] + part[2][t] + part[3][t];
    __syncthreads();
    if (t == 0) { __threadfence(); atomicExch(&g_flag[blk], 1); }

    // lookback: wait for all predecessors, then sum their aggregates
    if (t < c) while (atomicAdd(&g_flag[bh*NCHUNK + t], 0) == 0) {}
    __syncthreads();
    __threadfence();
    if (t < 64) {
        float o = 0.f;
        for (int cc = 0; cc < c; cc++) o += g_agg[(bh*NCHUNK + cc)*D + t];
        offs[0][t] = o;          o += part[0][t];
        offs[1][t] = o;          o += part[1][t];
        offs[2][t] = o;          o += part[2][t];
        offs[3][t] = o;
    }
    __syncthreads();

    for (int e = t; e < CHUNK*D/4; e += 256) {
        int q = e >> 4, d4 = e & 15;
        float4 v  = ((float4*)tile)[q*16 + d4];
        const float* ofp = &offs[q >> 5][d4*4];
        v.x += ofp[0]; v.y += ofp[1]; v.z += ofp[2]; v.w += ofp[3];
        *(float4*)(out + base + (size_t)q*HD + d4*4) = v;
    }
}

// ---------------------------------------------------------------------------
// Kernel 4: attention for the 40 selected queries per (b,h); scatter into out.
// Rank-i row attends only keys 0..i (Informer mask quirk: mask is triu(u,L)).
// Grid = (bh, group of 4 rows) = 320 blocks of 128; one warp per output row.
// Loads only the K/V rows its group can reference (0..4g+3).
// ---------------------------------------------------------------------------
__global__ void attn_kernel(const float* __restrict__ Q,
                            const float* __restrict__ K,
                            const float* __restrict__ V,
                            float* __restrict__ out) {
    int g  = blockIdx.x % 10;
    int bh = blockIdx.x / 10;
    int h  = bh & (H-1), b = bh >> 3;
    int t  = threadIdx.x;     // 128 = 4 warps
    __shared__ float Ks[U][D+1], Vs[U][D+1], Qs[4][D+1];
    __shared__ int ti[4];

    if (t < 4) ti[t] = g_top[bh*U + g*4 + t];
    __syncthreads();

    int kmax = g*4 + 4;                           // rows 0..kmax-1 needed
    for (int e = t; e < kmax*D; e += 128) {
        int r = e >> 6, d = e & 63;
        Ks[r][d] = K[((size_t)b*L + r)*HD + (size_t)h*D + d];
        Vs[r][d] = V[((size_t)b*L + r)*HD + (size_t)h*D + d];
    }
    for (int e = t; e < 4*D; e += 128) {
        int r = e >> 6, d = e & 63;
        Qs[r][d] = Q[((size_t)b*L + ti[r])*HD + (size_t)h*D + d];
    }
    __syncthreads();

    int warp = t >> 5, lane = t & 31;
    int i   = g*4 + warp;                         // output row rank 0..39
    int k1  = (lane < kmax) ? lane : 0;           // clamp to loaded rows
    int k2l = lane + 32;
    int k2  = (k2l < kmax) ? k2l : 0;

    bool v0 = (lane <= i);
    bool v1 = (k2l < U) && (k2l <= i);

    float s0 = 0.f, s1 = 0.f;
    #pragma unroll
    for (int d = 0; d < D; d++) {
        float qd = Qs[warp][d];
        s0 += qd * Ks[k1][d];
        s1 += qd * Ks[k2][d];
    }
    s0 *= SCALE; s1 *= SCALE;

    float mx = fmaxf(v0 ? s0 : -INFINITY, v1 ? s1 : -INFINITY);
    #pragma unroll
    for (int o = 16; o > 0; o >>= 1)
        mx = fmaxf(mx, __shfl_xor_sync(0xffffffffu, mx, o));

    float e0 = v0 ? __expf(s0 - mx) : 0.f;
    float e1 = v1 ? __expf(s1 - mx) : 0.f;
    float den = e0 + e1;
    #pragma unroll
    for (int o = 16; o > 0; o >>= 1)
        den += __shfl_xor_sync(0xffffffffu, den, o);
    float inv = __frcp_rn(den);
    float w0 = e0 * inv, w1 = e1 * inv;

    float a0 = 0.f, a1 = 0.f;
    int klim = (i < 31) ? i : 31;
    for (int k = 0; k <= klim; k++) {
        float w = __shfl_sync(0xffffffffu, w0, k);
        a0 += w * Vs[k][lane];
        a1 += w * Vs[k][lane+32];
    }
    for (int k = 32; k <= i; k++) {               // only when i >= 32
        float w = __shfl_sync(0xffffffffu, w1, k - 32);
        a0 += w * Vs[k][lane];
        a1 += w * Vs[k][lane+32];
    }

    float* op = out + ((size_t)b*L + ti[warp])*HD + (size_t)h*D;
    op[lane]      = a0;
    op[lane + 32] = a1;
}

// ---------------------------------------------------------------------------
// Launch: fork scan branch onto a second stream so the cumsum (V-only) runs
// concurrently with compute_M/topk (Q/K/idx-only); attn joins both.
// ---------------------------------------------------------------------------
extern "C" void kernel_launch(void* const* d_in, const int* in_sizes, int n_in,
                              void* d_out, int out_size) {
    const float* Q   = (const float*)d_in[0];
    const float* K   = (const float*)d_in[1];
    const float* V   = (const float*)d_in[2];
    const int*   idx = (const int*)d_in[3];
    float* out = (float*)d_out;

    static cudaStream_t s1 = nullptr;
    static cudaEvent_t  e_fork = nullptr, e_scan = nullptr;
    if (s1 == nullptr) {
        cudaStreamCreateWithFlags(&s1, cudaStreamNonBlocking);
        cudaEventCreateWithFlags(&e_fork, cudaEventDisableTiming);
        cudaEventCreateWithFlags(&e_scan, cudaEventDisableTiming);
    }

    // fork: scan branch on s1
    cudaEventRecord(e_fork, 0);
    cudaStreamWaitEvent(s1, e_fork, 0);
    clear_flags_kernel<<<1, B*H*NCHUNK, 0, s1>>>();
    scan_kernel<<<B*H*NCHUNK, 256, 0, s1>>>(V, out);
    cudaEventRecord(e_scan, s1);

    // main branch: M scores -> topk (independent of scan)
    compute_M_kernel<<<B*H*L*32/256, 256>>>(Q, K, idx);
    topk_kernel<<<B*H, 256>>>();

    // join: attn needs topk (same stream) and scan's out-writes (event)
    cudaStreamWaitEvent(0, e_scan, 0);
    attn_kernel<<<B*H*10, 128>>>(Q, K, V, out);
}

// round 16
// speedup vs baseline: 1.2164x; 1.1092x over previous
#include <cuda_runtime.h>
#include <math.h>

#define B 4
#define L 2048
#define H 8
#define D 64
#define S 40
#define U 40
#define HD (H*D)
#define CHUNK 128
#define NCHUNK (L/CHUNK)     /* 16 scan chunks */
#define SCALE 0.125f         /* 1/sqrt(64) */

// scratch (allocation-free rule: __device__ globals)
__device__ float g_M[B*H*L];
__device__ int   g_top[B*H*U];
__device__ float g_agg[B*H*NCHUNK*D];    // scan chunk aggregates
__device__ int   g_flag[B*H*NCHUNK];     // lookback flags

// ---------------------------------------------------------------------------
// Kernel 0: clear lookback flags (runs in scan stream, before scan).
// ---------------------------------------------------------------------------
__global__ void clear_flags_kernel() {
    g_flag[threadIdx.x] = 0;             // 512 threads = B*H*NCHUNK
}

// ---------------------------------------------------------------------------
// Kernel 1: M[b,h,q] = max_s dot(Q[b,h,q], K[b,h,idx[q,s]]) - sum_s/L
// One warp per (b,h,q). 4 groups of 8 lanes; each group owns one key per
// batch and reads its 256B row as 2x(8 lanes x 16B) = ONE 128B line per LDG.
// ---------------------------------------------------------------------------
__global__ void compute_M_kernel(const float* __restrict__ Q,
                                 const float* __restrict__ K,
                                 const int*   __restrict__ idx) {
    int gw   = (blockIdx.x * blockDim.x + threadIdx.x) >> 5;
    int lane = threadIdx.x & 31;
    if (gw >= B*H*L) return;
    int q = gw % L;
    int h = (gw / L) % H;
    int b = gw / (L*H);
    int g   = lane >> 3;     // group 0..3: which key in the batch
    int sub = lane & 7;      // 16B slice within the 128B half-row

    const float4* qrow = (const float4*)(Q + ((size_t)b*L + q)*HD + (size_t)h*D);
    float4 q0 = qrow[sub];        // dims [4*sub   .. 4*sub+3]
    float4 q1 = qrow[8 + sub];    // dims [32+4*sub .. ]

    int k0v = __ldg(idx + q*S + lane);
    int k1v = (lane < 8) ? __ldg(idx + q*S + 32 + lane) : 0;

    const size_t bhK = ((size_t)b*L)*HD + (size_t)h*D;

    float mx = -INFINITY, sm = 0.f;
    #pragma unroll
    for (int t = 0; t < 10; t++) {
        int srcl = t*4 + g;
        int kk = (srcl < 32) ? __shfl_sync(0xffffffffu, k0v, srcl)
                             : __shfl_sync(0xffffffffu, k1v, srcl - 32);
        const float4* krow = (const float4*)(K + bhK + (size_t)kk*HD);
        float4 k0 = krow[sub];
        float4 k1 = krow[8 + sub];
        float p = q0.x*k0.x + q0.y*k0.y + q0.z*k0.z + q0.w*k0.w
                + q1.x*k1.x + q1.y*k1.y + q1.z*k1.z + q1.w*k1.w;
        // reduce within the 8-lane group -> full 64-dim dot on every lane
        p += __shfl_xor_sync(0xffffffffu, p, 1);
        p += __shfl_xor_sync(0xffffffffu, p, 2);
        p += __shfl_xor_sync(0xffffffffu, p, 4);
        mx = fmaxf(mx, p);
        sm += p;
    }
    // reduce across the 4 groups
    mx = fmaxf(mx, __shfl_xor_sync(0xffffffffu, mx, 8));
    sm += __shfl_xor_sync(0xffffffffu, sm, 8);
    mx = fmaxf(mx, __shfl_xor_sync(0xffffffffu, mx, 16));
    sm += __shfl_xor_sync(0xffffffffu, sm, 16);

    if (lane == 0) g_M[gw] = mx - sm * (1.0f/(float)L);
}

// ---------------------------------------------------------------------------
// Kernel 2: top-40 per (b,h) via block-parallel 8-bit radix select (4 passes).
// 256 threads/bh, 8 register values each (order-preserving uint32 map).
// Per pass: 256-bin smem histogram of the current digit among prefix-matching
// values; warp 0 finds the threshold bin via shuffle suffix-scan. After 4
// passes s_prefix == exact 40th-largest value T. Then compact >T / ==T and
// rank pairwise (value desc, index asc == lax.top_k semantics).
// ---------------------------------------------------------------------------
__device__ __forceinline__ unsigned order_f32(float v) {
    unsigned u = __float_as_uint(v);
    return (u & 0x80000000u) ? ~u : (u | 0x80000000u);
}

__global__ void topk_kernel() {
    int bh = blockIdx.x;
    int t  = threadIdx.x;              // 256
    const float* M = g_M + bh*L;

    unsigned v[8];
    #pragma unroll
    for (int j = 0; j < 8; j++) v[j] = order_f32(M[j*256 + t]);

    __shared__ int      bins[256];
    __shared__ unsigned s_prefix;
    __shared__ int      s_k;
    if (t == 0) { s_prefix = 0u; s_k = U; }

    const unsigned hi_mask[4] = { 0u, 0xFF000000u, 0xFFFF0000u, 0xFFFFFF00u };

    #pragma unroll
    for (int pass = 0; pass < 4; pass++) {
        int shift = 24 - pass*8;
        bins[t] = 0;
        __syncthreads();
        unsigned pref = s_prefix, hm = hi_mask[pass];
        #pragma unroll
        for (int j = 0; j < 8; j++) {
            if ((v[j] & hm) == pref)
                atomicAdd(&bins[(v[j] >> shift) & 0xFF], 1);
        }
        __syncthreads();
        if (t < 32) {
            int k = s_k;
            int base = t*8;
            int cnt[8], gs = 0;
            #pragma unroll
            for (int i = 0; i < 8; i++) { cnt[i] = bins[base + i]; gs += cnt[i]; }
            // inclusive suffix sum across lanes (sum over lanes >= t)
            int suf = gs;
            #pragma unroll
            for (int o = 1; o < 32; o <<= 1) {
                int n = __shfl_down_sync(0xffffffffu, suf, o);
                if (t + o < 32) suf += n;
            }
            int above = suf - gs;          // count in lanes > t (higher digits)
            if (above < k && k <= suf) {   // threshold digit is in my group
                int acc = above, bsel = base;
                #pragma unroll
                for (int i = 7; i >= 0; i--) {
                    acc += cnt[i];
                    if (acc >= k) { bsel = base + i; break; }
                }
                s_prefix = pref | ((unsigned)(bsel - base + base - base + bsel & 0xFF) << shift);
                s_prefix = pref | (((unsigned)bsel & 0xFFu) << shift);
                s_k = k - (acc - bins[bsel]);   // rank within the tie digit
            }
        }
        __syncthreads();
    }
    unsigned T = s_prefix;             // exact 40th-largest value

    // compact candidates
    __shared__ int      nGT, nTie;
    __shared__ unsigned selval[48];
    __shared__ int      selidx[48], tieidx[48];
    if (t == 0) { nGT = 0; nTie = 0; }
    __syncthreads();
    #pragma unroll
    for (int j = 0; j < 8; j++) {
        if (v[j] > T) {
            int p = atomicAdd(&nGT, 1);
            if (p < 48) { selval[p] = v[j]; selidx[p] = j*256 + t; }
        } else if (v[j] == T) {
            int p = atomicAdd(&nTie, 1);
            if (p < 48) tieidx[p] = j*256 + t;
        }
    }
    __syncthreads();

    int n1 = nGT;                      // #elements strictly above T  (<= 39)
    int ntake = U - n1;                // #ties at T to take (smallest indices)

    // ranks for >T candidates: pairwise (value desc, index asc)
    if (t < n1) {
        unsigned mv = selval[t]; int mi = selidx[t];
        int r = 0;
        for (int j = 0; j < n1; j++) {
            unsigned ov2 = selval[j];
            r += (ov2 > mv) || (ov2 == mv && selidx[j] < mi);
        }
        g_top[bh*U + r] = mi;
    }
    // ties at T: smallest ntake indices get ranks n1..39 in ascending order
    if (t < 32) {
        int nt = (nTie < 48) ? nTie : 48;
        for (int i = t; i < nt; i += 32) {
            int mi = tieidx[i];
            int r = 0;
            for (int j = 0; j < nt; j++) r += (tieidx[j] < mi);
            if (r < ntake) g_top[bh*U + n1 + r] = mi;
        }
    }
}

// ---------------------------------------------------------------------------
// Kernel 3: fused cumsum(V) over L via decoupled lookback. One kernel, one V
// read, one out write. Block = (bh, c); all 512 blocks resident in one wave.
// (Exact form that passed at R7/R8/R13/R14/R15.)
// ---------------------------------------------------------------------------
__global__ void scan_kernel(const float* __restrict__ V, float* __restrict__ out) {
    int blk = blockIdx.x;
    int c   = blk & (NCHUNK-1);
    int bh  = blk >> 4;
    int h   = bh & (H-1), b = bh >> 3;
    int t   = threadIdx.x;            // 256
    __shared__ float tile[CHUNK*D];   // 32KB
    __shared__ float part[4][64];
    __shared__ float offs[4][64];

    size_t base = (((size_t)b*L + (size_t)c*CHUNK))*HD + (size_t)h*D;
    for (int e = t; e < CHUNK*D/4; e += 256) {
        int q = e >> 4, d4 = e & 15;
        ((float4*)tile)[q*16 + d4] = *(const float4*)(V + base + (size_t)q*HD + d4*4);
    }
    __syncthreads();

    // intra-part serial scan: 4 parts x 64 d-lanes, 32 rows each
    int p = t >> 6, d = t & 63;
    {
        float acc = 0.f;
        #pragma unroll
        for (int i = 0; i < 32; i++) {
            acc += tile[(p*32 + i)*64 + d];
            tile[(p*32 + i)*64 + d] = acc;
        }
        part[p][d] = acc;
    }
    __syncthreads();

    // publish chunk aggregate (release)
    if (t < 64) g_agg[blk*D + t] = part[0][t] + part[1][t] + part[2][t] + part[3][t];
    __syncthreads();
    if (t == 0) { __threadfence(); atomicExch(&g_flag[blk], 1); }

    // lookback: wait for all predecessors, then sum their aggregates
    if (t < c) while (atomicAdd(&g_flag[bh*NCHUNK + t], 0) == 0) {}
    __syncthreads();
    __threadfence();
    if (t < 64) {
        float o = 0.f;
        for (int cc = 0; cc < c; cc++) o += g_agg[(bh*NCHUNK + cc)*D + t];
        offs[0][t] = o;          o += part[0][t];
        offs[1][t] = o;          o += part[1][t];
        offs[2][t] = o;          o += part[2][t];
        offs[3][t] = o;
    }
    __syncthreads();

    for (int e = t; e < CHUNK*D/4; e += 256) {
        int q = e >> 4, d4 = e & 15;
        float4 v  = ((float4*)tile)[q*16 + d4];
        const float* ofp = &offs[q >> 5][d4*4];
        v.x += ofp[0]; v.y += ofp[1]; v.z += ofp[2]; v.w += ofp[3];
        *(float4*)(out + base + (size_t)q*HD + d4*4) = v;
    }
}

// ---------------------------------------------------------------------------
// Kernel 4: attention for the 40 selected queries per (b,h); scatter into out.
// Rank-i row attends only keys 0..i (Informer mask quirk: mask is triu(u,L)).
// Grid = (bh, group of 4 rows) = 320 blocks of 128; one warp per output row.
// Loads only the K/V rows its group can reference (0..4g+3).
// ---------------------------------------------------------------------------
__global__ void attn_kernel(const float* __restrict__ Q,
                            const float* __restrict__ K,
                            const float* __restrict__ V,
                            float* __restrict__ out) {
    int g  = blockIdx.x % 10;
    int bh = blockIdx.x / 10;
    int h  = bh & (H-1), b = bh >> 3;
    int t  = threadIdx.x;     // 128 = 4 warps
    __shared__ float Ks[U][D+1], Vs[U][D+1], Qs[4][D+1];
    __shared__ int ti[4];

    if (t < 4) ti[t] = g_top[bh*U + g*4 + t];
    __syncthreads();

    int kmax = g*4 + 4;                           // rows 0..kmax-1 needed
    for (int e = t; e < kmax*D; e += 128) {
        int r = e >> 6, d = e & 63;
        Ks[r][d] = K[((size_t)b*L + r)*HD + (size_t)h*D + d];
        Vs[r][d] = V[((size_t)b*L + r)*HD + (size_t)h*D + d];
    }
    for (int e = t; e < 4*D; e += 128) {
        int r = e >> 6, d = e & 63;
        Qs[r][d] = Q[((size_t)b*L + ti[r])*HD + (size_t)h*D + d];
    }
    __syncthreads();

    int warp = t >> 5, lane = t & 31;
    int i   = g*4 + warp;                         // output row rank 0..39
    int k1  = (lane < kmax) ? lane : 0;           // clamp to loaded rows
    int k2l = lane + 32;
    int k2  = (k2l < kmax) ? k2l : 0;

    bool v0 = (lane <= i);
    bool v1 = (k2l < U) && (k2l <= i);

    float s0 = 0.f, s1 = 0.f;
    #pragma unroll
    for (int d = 0; d < D; d++) {
        float qd = Qs[warp][d];
        s0 += qd * Ks[k1][d];
        s1 += qd * Ks[k2][d];
    }
    s0 *= SCALE; s1 *= SCALE;

    float mx = fmaxf(v0 ? s0 : -INFINITY, v1 ? s1 : -INFINITY);
    #pragma unroll
    for (int o = 16; o > 0; o >>= 1)
        mx = fmaxf(mx, __shfl_xor_sync(0xffffffffu, mx, o));

    float e0 = v0 ? __expf(s0 - mx) : 0.f;
    float e1 = v1 ? __expf(s1 - mx) : 0.f;
    float den = e0 + e1;
    #pragma unroll
    for (int o = 16; o > 0; o >>= 1)
        den += __shfl_xor_sync(0xffffffffu, den, o);
    float inv = __frcp_rn(den);
    float w0 = e0 * inv, w1 = e1 * inv;

    float a0 = 0.f, a1 = 0.f;
    int klim = (i < 31) ? i : 31;
    for (int k = 0; k <= klim; k++) {
        float w = __shfl_sync(0xffffffffu, w0, k);
        a0 += w * Vs[k][lane];
        a1 += w * Vs[k][lane+32];
    }
    for (int k = 32; k <= i; k++) {               // only when i >= 32
        float w = __shfl_sync(0xffffffffu, w1, k - 32);
        a0 += w * Vs[k][lane];
        a1 += w * Vs[k][lane+32];
    }

    float* op = out + ((size_t)b*L + ti[warp])*HD + (size_t)h*D;
    op[lane]      = a0;
    op[lane + 32] = a1;
}

// ---------------------------------------------------------------------------
// Launch: fork scan branch onto a second stream so the cumsum (V-only) runs
// concurrently with compute_M/topk (Q/K/idx-only); attn joins both.
// ---------------------------------------------------------------------------
extern "C" void kernel_launch(void* const* d_in, const int* in_sizes, int n_in,
                              void* d_out, int out_size) {
    const float* Q   = (const float*)d_in[0];
    const float* K   = (const float*)d_in[1];
    const float* V   = (const float*)d_in[2];
    const int*   idx = (const int*)d_in[3];
    float* out = (float*)d_out;

    static cudaStream_t s1 = nullptr;
    static cudaEvent_t  e_fork = nullptr, e_scan = nullptr;
    if (s1 == nullptr) {
        cudaStreamCreateWithFlags(&s1, cudaStreamNonBlocking);
        cudaEventCreateWithFlags(&e_fork, cudaEventDisableTiming);
        cudaEventCreateWithFlags(&e_scan, cudaEventDisableTiming);
    }

    // fork: scan branch on s1
    cudaEventRecord(e_fork, 0);
    cudaStreamWaitEvent(s1, e_fork, 0);
    clear_flags_kernel<<<1, B*H*NCHUNK, 0, s1>>>();
    scan_kernel<<<B*H*NCHUNK, 256, 0, s1>>>(V, out);
    cudaEventRecord(e_scan, s1);

    // main branch: M scores -> topk (independent of scan)
    compute_M_kernel<<<B*H*L*32/256, 256>>>(Q, K, idx);
    topk_kernel<<<B*H, 256>>>();

    // join: attn needs topk (same stream) and scan's out-writes (event)
    cudaStreamWaitEvent(0, e_scan, 0);
    attn_kernel<<<B*H*10, 128>>>(Q, K, V, out);
}

// round 17
// speedup vs baseline: 1.2238x; 1.0061x over previous
#include <cuda_runtime.h>
#include <math.h>

#define B 4
#define L 2048
#define H 8
#define D 64
#define S 40
#define U 40
#define HD (H*D)
#define CHUNK 128
#define NCHUNK (L/CHUNK)     /* 16 scan chunks */
#define SCALE 0.125f         /* 1/sqrt(64) */

// scratch (allocation-free rule: __device__ globals)
__device__ float g_M[B*H*L];
__device__ int   g_top[B*H*U];
__device__ float g_agg[B*H*NCHUNK*D];    // scan chunk aggregates
__device__ int   g_flag[B*H*NCHUNK];     // lookback flags

// ---------------------------------------------------------------------------
// Kernel 0: clear lookback flags (runs in scan stream, before scan).
// ---------------------------------------------------------------------------
__global__ void clear_flags_kernel() {
    g_flag[threadIdx.x] = 0;             // 512 threads = B*H*NCHUNK
}

// ---------------------------------------------------------------------------
// Kernel 1: M[b,h,q] = max_s dot(Q[b,h,q], K[b,h,idx[q,s]]) - sum_s/L
// One warp per (b,h,q). 4 groups of 8 lanes; each group owns one key per
// batch and reads its 256B row as 2x(8 lanes x 16B) = ONE 128B line per LDG.
// ---------------------------------------------------------------------------
__global__ void compute_M_kernel(const float* __restrict__ Q,
                                 const float* __restrict__ K,
                                 const int*   __restrict__ idx) {
    int gw   = (blockIdx.x * blockDim.x + threadIdx.x) >> 5;
    int lane = threadIdx.x & 31;
    if (gw >= B*H*L) return;
    int q = gw % L;
    int h = (gw / L) % H;
    int b = gw / (L*H);
    int g   = lane >> 3;     // group 0..3: which key in the batch
    int sub = lane & 7;      // 16B slice within the 128B half-row

    const float4* qrow = (const float4*)(Q + ((size_t)b*L + q)*HD + (size_t)h*D);
    float4 q0 = qrow[sub];        // dims [4*sub   .. 4*sub+3]
    float4 q1 = qrow[8 + sub];    // dims [32+4*sub .. ]

    int k0v = __ldg(idx + q*S + lane);
    int k1v = (lane < 8) ? __ldg(idx + q*S + 32 + lane) : 0;

    const size_t bhK = ((size_t)b*L)*HD + (size_t)h*D;

    float mx = -INFINITY, sm = 0.f;
    #pragma unroll
    for (int t = 0; t < 10; t++) {
        int srcl = t*4 + g;
        int kk = (srcl < 32) ? __shfl_sync(0xffffffffu, k0v, srcl)
                             : __shfl_sync(0xffffffffu, k1v, srcl - 32);
        const float4* krow = (const float4*)(K + bhK + (size_t)kk*HD);
        float4 k0 = krow[sub];
        float4 k1 = krow[8 + sub];
        float p = q0.x*k0.x + q0.y*k0.y + q0.z*k0.z + q0.w*k0.w
                + q1.x*k1.x + q1.y*k1.y + q1.z*k1.z + q1.w*k1.w;
        // reduce within the 8-lane group -> full 64-dim dot on every lane
        p += __shfl_xor_sync(0xffffffffu, p, 1);
        p += __shfl_xor_sync(0xffffffffu, p, 2);
        p += __shfl_xor_sync(0xffffffffu, p, 4);
        mx = fmaxf(mx, p);
        sm += p;
    }
    // reduce across the 4 groups
    mx = fmaxf(mx, __shfl_xor_sync(0xffffffffu, mx, 8));
    sm += __shfl_xor_sync(0xffffffffu, sm, 8);
    mx = fmaxf(mx, __shfl_xor_sync(0xffffffffu, mx, 16));
    sm += __shfl_xor_sync(0xffffffffu, sm, 16);

    if (lane == 0) g_M[gw] = mx - sm * (1.0f/(float)L);
}

// ---------------------------------------------------------------------------
// Kernel 2: top-40 per (b,h) via block-parallel 8-bit radix select (4 passes).
// 256 threads/bh, 8 register values each (order-preserving uint32 map).
// Per pass: 256-bin smem histogram of the current digit among prefix-matching
// values; warp 0 finds the threshold bin via shuffle suffix-scan. After 4
// passes s_prefix == exact 40th-largest value T. Then compact >T / ==T and
// rank pairwise (value desc, index asc == lax.top_k semantics).
// ---------------------------------------------------------------------------
__device__ __forceinline__ unsigned order_f32(float v) {
    unsigned u = __float_as_uint(v);
    return (u & 0x80000000u) ? ~u : (u | 0x80000000u);
}

__global__ void topk_kernel() {
    int bh = blockIdx.x;
    int t  = threadIdx.x;              // 256
    const float* M = g_M + bh*L;

    unsigned v[8];
    #pragma unroll
    for (int j = 0; j < 8; j++) v[j] = order_f32(M[j*256 + t]);

    __shared__ int      bins[256];
    __shared__ unsigned s_prefix;
    __shared__ int      s_k;
    if (t == 0) { s_prefix = 0u; s_k = U; }

    const unsigned hi_mask[4] = { 0u, 0xFF000000u, 0xFFFF0000u, 0xFFFFFF00u };

    #pragma unroll
    for (int pass = 0; pass < 4; pass++) {
        int shift = 24 - pass*8;
        bins[t] = 0;
        __syncthreads();
        unsigned pref = s_prefix, hm = hi_mask[pass];
        #pragma unroll
        for (int j = 0; j < 8; j++) {
            if ((v[j] & hm) == pref)
                atomicAdd(&bins[(v[j] >> shift) & 0xFF], 1);
        }
        __syncthreads();
        if (t < 32) {
            int k = s_k;
            int base = t*8;
            int cnt[8], gs = 0;
            #pragma unroll
            for (int i = 0; i < 8; i++) { cnt[i] = bins[base + i]; gs += cnt[i]; }
            // inclusive suffix sum across lanes (sum over lanes >= t)
            int suf = gs;
            #pragma unroll
            for (int o = 1; o < 32; o <<= 1) {
                int n = __shfl_down_sync(0xffffffffu, suf, o);
                if (t + o < 32) suf += n;
            }
            int above = suf - gs;          // count in lanes > t (higher digits)
            if (above < k && k <= suf) {   // threshold digit is in my group
                int acc = above, bsel = base;
                #pragma unroll
                for (int i = 7; i >= 0; i--) {
                    acc += cnt[i];
                    if (acc >= k) { bsel = base + i; break; }
                }
                s_prefix = pref | (((unsigned)bsel & 0xFFu) << shift);
                s_k = k - (acc - bins[bsel]);   // rank within the tie digit
            }
        }
        __syncthreads();
    }
    unsigned T = s_prefix;             // exact 40th-largest value

    // compact candidates
    __shared__ int      nGT, nTie;
    __shared__ unsigned selval[48];
    __shared__ int      selidx[48], tieidx[48];
    if (t == 0) { nGT = 0; nTie = 0; }
    __syncthreads();
    #pragma unroll
    for (int j = 0; j < 8; j++) {
        if (v[j] > T) {
            int p = atomicAdd(&nGT, 1);
            if (p < 48) { selval[p] = v[j]; selidx[p] = j*256 + t; }
        } else if (v[j] == T) {
            int p = atomicAdd(&nTie, 1);
            if (p < 48) tieidx[p] = j*256 + t;
        }
    }
    __syncthreads();

    int n1 = nGT;                      // #elements strictly above T  (<= 39)
    int ntake = U - n1;                // #ties at T to take (smallest indices)

    // ranks for >T candidates: pairwise (value desc, index asc)
    if (t < n1) {
        unsigned mv = selval[t]; int mi = selidx[t];
        int r = 0;
        for (int j = 0; j < n1; j++) {
            unsigned ov2 = selval[j];
            r += (ov2 > mv) || (ov2 == mv && selidx[j] < mi);
        }
        g_top[bh*U + r] = mi;
    }
    // ties at T: smallest ntake indices get ranks n1..39 in ascending order
    if (t < 32) {
        int nt = (nTie < 48) ? nTie : 48;
        for (int i = t; i < nt; i += 32) {
            int mi = tieidx[i];
            int r = 0;
            for (int j = 0; j < nt; j++) r += (tieidx[j] < mi);
            if (r < ntake) g_top[bh*U + n1 + r] = mi;
        }
    }
}

// ---------------------------------------------------------------------------
// Kernel 3: fused cumsum(V) over L via decoupled lookback. One kernel, one V
// read, one out write. Block = (bh, c); all 512 blocks resident in one wave.
// (Exact form that passed at R7/R8/R13/R14/R15/R16.)
// ---------------------------------------------------------------------------
__global__ void scan_kernel(const float* __restrict__ V, float* __restrict__ out) {
    int blk = blockIdx.x;
    int c   = blk & (NCHUNK-1);
    int bh  = blk >> 4;
    int h   = bh & (H-1), b = bh >> 3;
    int t   = threadIdx.x;            // 256
    __shared__ float tile[CHUNK*D];   // 32KB
    __shared__ float part[4][64];
    __shared__ float offs[4][64];

    size_t base = (((size_t)b*L + (size_t)c*CHUNK))*HD + (size_t)h*D;
    for (int e = t; e < CHUNK*D/4; e += 256) {
        int q = e >> 4, d4 = e & 15;
        ((float4*)tile)[q*16 + d4] = *(const float4*)(V + base + (size_t)q*HD + d4*4);
    }
    __syncthreads();

    // intra-part serial scan: 4 parts x 64 d-lanes, 32 rows each
    int p = t >> 6, d = t & 63;
    {
        float acc = 0.f;
        #pragma unroll
        for (int i = 0; i < 32; i++) {
            acc += tile[(p*32 + i)*64 + d];
            tile[(p*32 + i)*64 + d] = acc;
        }
        part[p][d] = acc;
    }
    __syncthreads();

    // publish chunk aggregate (release)
    if (t < 64) g_agg[blk*D + t] = part[0][t] + part[1][t] + part[2][t] + part[3][t];
    __syncthreads();
    if (t == 0) { __threadfence(); atomicExch(&g_flag[blk], 1); }

    // lookback: wait for all predecessors, then sum their aggregates
    if (t < c) while (atomicAdd(&g_flag[bh*NCHUNK + t], 0) == 0) {}
    __syncthreads();
    __threadfence();
    if (t < 64) {
        float o = 0.f;
        for (int cc = 0; cc < c; cc++) o += g_agg[(bh*NCHUNK + cc)*D + t];
        offs[0][t] = o;          o += part[0][t];
        offs[1][t] = o;          o += part[1][t];
        offs[2][t] = o;          o += part[2][t];
        offs[3][t] = o;
    }
    __syncthreads();

    for (int e = t; e < CHUNK*D/4; e += 256) {
        int q = e >> 4, d4 = e & 15;
        float4 v  = ((float4*)tile)[q*16 + d4];
        const float* ofp = &offs[q >> 5][d4*4];
        v.x += ofp[0]; v.y += ofp[1]; v.z += ofp[2]; v.w += ofp[3];
        *(float4*)(out + base + (size_t)q*HD + d4*4) = v;
    }
}

// ---------------------------------------------------------------------------
// Kernel 4: attention for the 40 selected queries per (b,h); scatter into out.
// Rank-i row attends only keys 0..i (Informer mask quirk: mask is triu(u,L)).
// Grid = (bh, group of 4 rows) = 320 blocks of 128; one warp per output row.
// PDL: launched with programmatic stream serialization — the K/V staging
// preamble overlaps the preceding topk kernel; cudaGridDependencySynchronize
// gates the g_top read. (Falls back to plain serialization if unsupported.)
// ---------------------------------------------------------------------------
__global__ void attn_kernel(const float* __restrict__ Q,
                            const float* __restrict__ K,
                            const float* __restrict__ V,
                            float* __restrict__ out) {
    int g  = blockIdx.x % 10;
    int bh = blockIdx.x / 10;
    int h  = bh & (H-1), b = bh >> 3;
    int t  = threadIdx.x;     // 128 = 4 warps
    __shared__ float Ks[U][D+1], Vs[U][D+1], Qs[4][D+1];
    __shared__ int ti[4];

    // ---- preamble: stage K/V rows 0..kmax-1 (independent of topk) ----
    int kmax = g*4 + 4;
    for (int e = t; e < kmax*D; e += 128) {
        int r = e >> 6, d = e & 63;
        Ks[r][d] = K[((size_t)b*L + r)*HD + (size_t)h*D + d];
        Vs[r][d] = V[((size_t)b*L + r)*HD + (size_t)h*D + d];
    }

    // ---- wait for topk (PDL join), then consume g_top ----
    cudaGridDependencySynchronize();
    if (t < 4) ti[t] = g_top[bh*U + g*4 + t];
    __syncthreads();                   // covers staging + ti

    int warp = t >> 5, lane = t & 31;
    {   // each warp stages its own Q row
        const float* qp = Q + ((size_t)b*L + ti[warp])*HD + (size_t)h*D;
        Qs[warp][lane]      = qp[lane];
        Qs[warp][lane + 32] = qp[lane + 32];
        __syncwarp();
    }

    int i   = g*4 + warp;                         // output row rank 0..39
    int k1  = (lane < kmax) ? lane : 0;           // clamp to loaded rows
    int k2l = lane + 32;
    int k2  = (k2l < kmax) ? k2l : 0;

    bool v0 = (lane <= i);
    bool v1 = (k2l < U) && (k2l <= i);

    float s0 = 0.f, s1 = 0.f;
    #pragma unroll
    for (int d = 0; d < D; d++) {
        float qd = Qs[warp][d];
        s0 += qd * Ks[k1][d];
        s1 += qd * Ks[k2][d];
    }
    s0 *= SCALE; s1 *= SCALE;

    float mx = fmaxf(v0 ? s0 : -INFINITY, v1 ? s1 : -INFINITY);
    #pragma unroll
    for (int o = 16; o > 0; o >>= 1)
        mx = fmaxf(mx, __shfl_xor_sync(0xffffffffu, mx, o));

    float e0 = v0 ? __expf(s0 - mx) : 0.f;
    float e1 = v1 ? __expf(s1 - mx) : 0.f;
    float den = e0 + e1;
    #pragma unroll
    for (int o = 16; o > 0; o >>= 1)
        den += __shfl_xor_sync(0xffffffffu, den, o);
    float inv = __frcp_rn(den);
    float w0 = e0 * inv, w1 = e1 * inv;

    float a0 = 0.f, a1 = 0.f;
    int klim = (i < 31) ? i : 31;
    for (int k = 0; k <= klim; k++) {
        float w = __shfl_sync(0xffffffffu, w0, k);
        a0 += w * Vs[k][lane];
        a1 += w * Vs[k][lane+32];
    }
    for (int k = 32; k <= i; k++) {               // only when i >= 32
        float w = __shfl_sync(0xffffffffu, w1, k - 32);
        a0 += w * Vs[k][lane];
        a1 += w * Vs[k][lane+32];
    }

    float* op = out + ((size_t)b*L + ti[warp])*HD + (size_t)h*D;
    op[lane]      = a0;
    op[lane + 32] = a1;
}

// ---------------------------------------------------------------------------
// Launch: fork scan branch onto a second stream (V-only, overlaps compute_M);
// attn joins scan via event and overlaps topk via PDL.
// ---------------------------------------------------------------------------
extern "C" void kernel_launch(void* const* d_in, const int* in_sizes, int n_in,
                              void* d_out, int out_size) {
    const float* Q   = (const float*)d_in[0];
    const float* K   = (const float*)d_in[1];
    const float* V   = (const float*)d_in[2];
    const int*   idx = (const int*)d_in[3];
    float* out = (float*)d_out;

    static cudaStream_t s1 = nullptr;
    static cudaEvent_t  e_fork = nullptr, e_scan = nullptr;
    if (s1 == nullptr) {
        cudaStreamCreateWithFlags(&s1, cudaStreamNonBlocking);
        cudaEventCreateWithFlags(&e_fork, cudaEventDisableTiming);
        cudaEventCreateWithFlags(&e_scan, cudaEventDisableTiming);
    }

    // fork: scan branch on s1
    cudaEventRecord(e_fork, 0);
    cudaStreamWaitEvent(s1, e_fork, 0);
    clear_flags_kernel<<<1, B*H*NCHUNK, 0, s1>>>();
    scan_kernel<<<B*H*NCHUNK, 256, 0, s1>>>(V, out);
    cudaEventRecord(e_scan, s1);

    // main branch: M scores -> topk (independent of scan)
    compute_M_kernel<<<B*H*L*32/256, 256>>>(Q, K, idx);
    topk_kernel<<<B*H, 256>>>();

    // join: attn needs topk (PDL-relaxed) and scan's out-writes (event)
    cudaStreamWaitEvent(0, e_scan, 0);
    {
        cudaLaunchConfig_t cfg = {};
        cfg.gridDim  = dim3(B*H*10);
        cfg.blockDim = dim3(128);
        cfg.stream   = 0;
        cudaLaunchAttribute at[1];
        at[0].id = cudaLaunchAttributeProgrammaticStreamSerialization;
        at[0].val.programmaticStreamSerializationAllowed = 1;
        cfg.attrs = at;
        cfg.numAttrs = 1;
        cudaLaunchKernelEx(&cfg, attn_kernel, Q, K, V, out);
    }
}